// round 15
// baseline (speedup 1.0000x reference)
#include <cuda_runtime.h>
#include <cuda_fp16.h>
#include <stdint.h>
#include <math.h>

#define F_IN  256
#define HID   128
#define C_OUT 40
#define NMAX  100000
#define EMAX  3200000
#define SCAN_BLK 1024

// Scratch (allocation-free rule: __device__ globals)
__device__ __half g_h1[(size_t)NMAX * HID];    // x @ W1, fp16
__device__ __half g_agg1[(size_t)NMAX * HID];  // relu(agg + b1), fp16
__device__ __half g_h2[(size_t)NMAX * C_OUT];  // agg1 @ W2, fp16

// CSR scratch
__device__ int   g_cnt[NMAX];
__device__ int   g_rowptr[NMAX + 1];
__device__ int   g_cursor[NMAX];
__device__ int   g_partial[(NMAX + SCAN_BLK - 1) / SCAN_BLK];
__device__ int   g_offs[(NMAX + SCAN_BLK - 1) / SCAN_BLK];
__device__ uint2 g_csr[EMAX];   // .x = src, .y = weight bits

// ---------------------------------------------------------------------------
// helpers
// ---------------------------------------------------------------------------
__device__ __forceinline__ uint32_t f2tf32(float x) {
  uint32_t r;
  asm("cvt.rna.tf32.f32 %0, %1;" : "=r"(r) : "f"(x));
  return r;
}

__device__ __forceinline__ void mma_tf32(
    float* d, const uint32_t* a, const uint32_t* b, const float* c) {
  asm volatile(
      "mma.sync.aligned.m16n8k8.row.col.f32.tf32.tf32.f32 "
      "{%0,%1,%2,%3}, {%4,%5,%6,%7}, {%8,%9}, {%10,%11,%12,%13};"
      : "=f"(d[0]), "=f"(d[1]), "=f"(d[2]), "=f"(d[3])
      : "r"(a[0]), "r"(a[1]), "r"(a[2]), "r"(a[3]),
        "r"(b[0]), "r"(b[1]),
        "f"(c[0]), "f"(c[1]), "f"(c[2]), "f"(c[3]));
}

__device__ __forceinline__ void mma_f16(
    float* d, const uint32_t* a, const uint32_t* b, const float* c) {
  asm volatile(
      "mma.sync.aligned.m16n8k16.row.col.f32.f16.f16.f32 "
      "{%0,%1,%2,%3}, {%4,%5,%6,%7}, {%8,%9}, {%10,%11,%12,%13};"
      : "=f"(d[0]), "=f"(d[1]), "=f"(d[2]), "=f"(d[3])
      : "r"(a[0]), "r"(a[1]), "r"(a[2]), "r"(a[3]),
        "r"(b[0]), "r"(b[1]),
        "f"(c[0]), "f"(c[1]), "f"(c[2]), "f"(c[3]));
}

__device__ __forceinline__ void ldsm_x4(uint32_t* r, uint32_t addr) {
  asm volatile("ldmatrix.sync.aligned.m8n8.x4.shared.b16 {%0,%1,%2,%3}, [%4];"
               : "=r"(r[0]), "=r"(r[1]), "=r"(r[2]), "=r"(r[3]) : "r"(addr));
}

__device__ __forceinline__ void ldsm_x4_trans(uint32_t* r, uint32_t addr) {
  asm volatile("ldmatrix.sync.aligned.m8n8.x4.trans.shared.b16 {%0,%1,%2,%3}, [%4];"
               : "=r"(r[0]), "=r"(r[1]), "=r"(r[2]), "=r"(r[3]) : "r"(addr));
}

// ---------------------------------------------------------------------------
// GEMM1: H1[M,128] = X[M,256] @ W1[256,128]
// fp16 MMA (m16n8k16) + ldmatrix, REGISTER double-buffered staging:
// global loads for chunk c+1 issue right after the barriers, overlapping
// the 64 MMAs of chunk c (hides DRAM latency without cp.async).
// ---------------------------------------------------------------------------
#define G1_BK 32
__global__ __launch_bounds__(256) void gemm1_kernel(
    const float* __restrict__ X, const float* __restrict__ W, int M) {
  __shared__ __half As[128][G1_BK + 8];
  __shared__ __half Bs[G1_BK][HID + 8];

  const int t = threadIdx.x;
  const int row0 = blockIdx.x * 128;
  const int warp = t >> 5;
  const int lane = t & 31;
  const int g  = lane >> 2;
  const int tg = lane & 3;
  const int m_base = (warp & 3) * 32;
  const int n_base = (warp >> 2) * 64;
  const int l15 = lane & 15;
  const int lhi = (lane >> 4) << 3;  // 0 or 8

  // Per-thread staging coords (8 float2 each for A and B)
  int arow[8], acol[8], brow[8], bcol[8];
  const float* aptr[8];
#pragma unroll
  for (int i = 0; i < 8; i++) {
    int id = t + i * 256;
    arow[i] = id >> 4;            // 0..127
    acol[i] = (id & 15) * 2;      // 0..30
    int grow = row0 + arow[i];
    if (grow >= M) grow = M - 1;
    aptr[i] = X + (size_t)grow * F_IN + acol[i];
    brow[i] = id >> 6;            // 0..31
    bcol[i] = (id & 63) * 2;      // 0..126
  }

  float acc[2][8][4];
#pragma unroll
  for (int mt = 0; mt < 2; mt++)
#pragma unroll
    for (int nt = 0; nt < 8; nt++)
#pragma unroll
      for (int i = 0; i < 4; i++) acc[mt][nt][i] = 0.f;

  // Prologue: load chunk 0 into registers
  float2 aReg[8], bReg[8];
#pragma unroll
  for (int i = 0; i < 8; i++) {
    aReg[i] = *(const float2*)(aptr[i]);
    bReg[i] = *(const float2*)(W + (size_t)brow[i] * HID + bcol[i]);
  }

  const int NCHUNK = F_IN / G1_BK;  // 8
#pragma unroll 1
  for (int c = 0; c < NCHUNK; c++) {
    // Store current chunk regs -> smem (fp16)
#pragma unroll
    for (int i = 0; i < 8; i++) {
      *(__half2*)&As[arow[i]][acol[i]] = __floats2half2_rn(aReg[i].x, aReg[i].y);
      *(__half2*)&Bs[brow[i]][bcol[i]] = __floats2half2_rn(bReg[i].x, bReg[i].y);
    }
    __syncthreads();

    // Issue next chunk's global loads (overlap with MMAs below)
    if (c + 1 < NCHUNK) {
      int k0n = (c + 1) * G1_BK;
#pragma unroll
      for (int i = 0; i < 8; i++) {
        aReg[i] = *(const float2*)(aptr[i] + k0n);
        bReg[i] = *(const float2*)(W + (size_t)(k0n + brow[i]) * HID + bcol[i]);
      }
    }

    // Compute chunk c
#pragma unroll
    for (int kk = 0; kk < 2; kk++) {   // two k16 steps
      const int kb = kk * 16;
      uint32_t a[2][4];
#pragma unroll
      for (int mt = 0; mt < 2; mt++) {
        uint32_t addr = (uint32_t)__cvta_generic_to_shared(
            &As[m_base + mt * 16 + l15][kb + lhi]);
        ldsm_x4(a[mt], addr);
      }
#pragma unroll
      for (int p = 0; p < 4; p++) {
        uint32_t b[4];
        uint32_t addr = (uint32_t)__cvta_generic_to_shared(
            &Bs[kb + l15][n_base + p * 16 + lhi]);
        ldsm_x4_trans(b, addr);
        mma_f16(acc[0][2 * p    ], a[0], b + 0, acc[0][2 * p    ]);
        mma_f16(acc[0][2 * p + 1], a[0], b + 2, acc[0][2 * p + 1]);
        mma_f16(acc[1][2 * p    ], a[1], b + 0, acc[1][2 * p    ]);
        mma_f16(acc[1][2 * p + 1], a[1], b + 2, acc[1][2 * p + 1]);
      }
    }
    __syncthreads();
  }

#pragma unroll
  for (int mt = 0; mt < 2; mt++) {
    int r1 = row0 + m_base + mt * 16 + g;
    int r2 = r1 + 8;
#pragma unroll
    for (int nt = 0; nt < 8; nt++) {
      int col = n_base + nt * 8 + tg * 2;
      if (r1 < M) *(__half2*)(g_h1 + (size_t)r1 * HID + col) =
          __floats2half2_rn(acc[mt][nt][0], acc[mt][nt][1]);
      if (r2 < M) *(__half2*)(g_h1 + (size_t)r2 * HID + col) =
          __floats2half2_rn(acc[mt][nt][2], acc[mt][nt][3]);
    }
  }
}

// ---------------------------------------------------------------------------
// CSR build (R7-proven 3-phase scan; single stream)
// ---------------------------------------------------------------------------
__global__ void zero_cnt_kernel(int M) {
  int i = blockIdx.x * blockDim.x + threadIdx.x;
  if (i < M) g_cnt[i] = 0;
}

__global__ void hist_kernel(const int* __restrict__ dst4, int E) {
  int i = blockIdx.x * blockDim.x + threadIdx.x;
  int e = i * 4;
  if (e + 4 <= E) {
    int4 d = *(const int4*)(dst4 + e);
    atomicAdd(&g_cnt[d.x], 1);
    atomicAdd(&g_cnt[d.y], 1);
    atomicAdd(&g_cnt[d.z], 1);
    atomicAdd(&g_cnt[d.w], 1);
  } else {
    for (; e < E; e++) atomicAdd(&g_cnt[__ldg(dst4 + e)], 1);
  }
}

__global__ __launch_bounds__(SCAN_BLK) void scanA_kernel(int M) {
  __shared__ int s[SCAN_BLK];
  int t = threadIdx.x;
  int i = blockIdx.x * SCAN_BLK + t;
  int v = (i < M) ? g_cnt[i] : 0;
  s[t] = v;
  __syncthreads();
#pragma unroll
  for (int d = SCAN_BLK / 2; d > 0; d >>= 1) {
    if (t < d) s[t] += s[t + d];
    __syncthreads();
  }
  if (t == 0) g_partial[blockIdx.x] = s[0];
}

__global__ __launch_bounds__(SCAN_BLK) void scanB_kernel(int nblk, int M, int E) {
  __shared__ int s[2][SCAN_BLK];
  int t = threadIdx.x;
  int v = (t < nblk) ? g_partial[t] : 0;
  s[0][t] = v;
  __syncthreads();
  int cur = 0;
#pragma unroll
  for (int d = 1; d < SCAN_BLK; d <<= 1) {
    int nxt = cur ^ 1;
    int val = s[cur][t];
    if (t >= d) val += s[cur][t - d];
    s[nxt][t] = val;
    __syncthreads();
    cur = nxt;
  }
  if (t < nblk) g_offs[t] = s[cur][t] - v;
  if (t == 0) g_rowptr[M] = E;
}

__global__ __launch_bounds__(SCAN_BLK) void scanC_kernel(int M) {
  __shared__ int s[2][SCAN_BLK];
  int t = threadIdx.x;
  int i = blockIdx.x * SCAN_BLK + t;
  int v = (i < M) ? g_cnt[i] : 0;
  s[0][t] = v;
  __syncthreads();
  int cur = 0;
#pragma unroll
  for (int d = 1; d < SCAN_BLK; d <<= 1) {
    int nxt = cur ^ 1;
    int val = s[cur][t];
    if (t >= d) val += s[cur][t - d];
    s[nxt][t] = val;
    __syncthreads();
    cur = nxt;
  }
  if (i < M) {
    int excl = s[cur][t] - v + g_offs[blockIdx.x];
    g_rowptr[i] = excl;
    g_cursor[i] = excl;
  }
}

__global__ void fill_kernel(const int* __restrict__ ei,
                            const float* __restrict__ ew, int E) {
  int i = blockIdx.x * blockDim.x + threadIdx.x;
  int e = i * 2;
  if (e + 2 <= E) {
    int2   s = *(const int2*)(ei + e);
    int2   d = *(const int2*)(ei + E + e);
    float2 w = *(const float2*)(ew + e);
    int p0 = atomicAdd(&g_cursor[d.x], 1);
    g_csr[p0] = make_uint2((unsigned)s.x, __float_as_uint(w.x));
    int p1 = atomicAdd(&g_cursor[d.y], 1);
    g_csr[p1] = make_uint2((unsigned)s.y, __float_as_uint(w.y));
  } else {
    for (; e < E; e++) {
      int src = __ldg(ei + e);
      int dst = __ldg(ei + E + e);
      int pos = atomicAdd(&g_cursor[dst], 1);
      g_csr[pos] = make_uint2((unsigned)src, __float_as_uint(__ldg(ew + e)));
    }
  }
}

// ---------------------------------------------------------------------------
// agg1: one warp per dst row; fp16 gather, fp32 accumulate; unroll 8 (MLP).
// Fused: +b1, ReLU; output stored fp16.
// ---------------------------------------------------------------------------
__device__ __forceinline__ void acc_h1(float4& acc, float w, uint2 u) {
  float2 lo = __half22float2(*(__half2*)&u.x);
  float2 hi = __half22float2(*(__half2*)&u.y);
  acc.x += w * lo.x; acc.y += w * lo.y;
  acc.z += w * hi.x; acc.w += w * hi.y;
}

__global__ __launch_bounds__(256) void agg1_kernel(
    const float* __restrict__ b1, int M) {
  int row = blockIdx.x * 8 + (threadIdx.x >> 5);
  if (row >= M) return;
  int lane = threadIdx.x & 31;
  int beg = g_rowptr[row];
  int end = g_rowptr[row + 1];

  float4 acc = *(const float4*)(b1 + lane * 4);

  const uint2* h1p = (const uint2*)g_h1;
  int e = beg;
  for (; e + 8 <= end; e += 8) {
    uint2 c0 = __ldg(&g_csr[e]),     c1 = __ldg(&g_csr[e + 1]);
    uint2 c2 = __ldg(&g_csr[e + 2]), c3 = __ldg(&g_csr[e + 3]);
    uint2 c4 = __ldg(&g_csr[e + 4]), c5 = __ldg(&g_csr[e + 5]);
    uint2 c6 = __ldg(&g_csr[e + 6]), c7 = __ldg(&g_csr[e + 7]);
    uint2 u0 = __ldg(h1p + (size_t)c0.x * 32 + lane);
    uint2 u1 = __ldg(h1p + (size_t)c1.x * 32 + lane);
    uint2 u2 = __ldg(h1p + (size_t)c2.x * 32 + lane);
    uint2 u3 = __ldg(h1p + (size_t)c3.x * 32 + lane);
    uint2 u4 = __ldg(h1p + (size_t)c4.x * 32 + lane);
    uint2 u5 = __ldg(h1p + (size_t)c5.x * 32 + lane);
    uint2 u6 = __ldg(h1p + (size_t)c6.x * 32 + lane);
    uint2 u7 = __ldg(h1p + (size_t)c7.x * 32 + lane);
    acc_h1(acc, __uint_as_float(c0.y), u0);
    acc_h1(acc, __uint_as_float(c1.y), u1);
    acc_h1(acc, __uint_as_float(c2.y), u2);
    acc_h1(acc, __uint_as_float(c3.y), u3);
    acc_h1(acc, __uint_as_float(c4.y), u4);
    acc_h1(acc, __uint_as_float(c5.y), u5);
    acc_h1(acc, __uint_as_float(c6.y), u6);
    acc_h1(acc, __uint_as_float(c7.y), u7);
  }
  for (; e < end; e++) {
    uint2 c0 = __ldg(&g_csr[e]);
    uint2 u0 = __ldg(h1p + (size_t)c0.x * 32 + lane);
    acc_h1(acc, __uint_as_float(c0.y), u0);
  }
  acc.x = fmaxf(acc.x, 0.f); acc.y = fmaxf(acc.y, 0.f);
  acc.z = fmaxf(acc.z, 0.f); acc.w = fmaxf(acc.w, 0.f);
  __half2 h01 = __floats2half2_rn(acc.x, acc.y);
  __half2 h23 = __floats2half2_rn(acc.z, acc.w);
  uint2 pack = make_uint2(*(uint32_t*)&h01, *(uint32_t*)&h23);
  *(uint2*)(g_agg1 + (size_t)row * HID + lane * 4) = pack;
}

// ---------------------------------------------------------------------------
// GEMM2: H2[M,40] = agg1[M,128] @ W2[128,40], tf32 MMA (RNA cvt), fp16 in/out.
// ---------------------------------------------------------------------------
#define G2_BK 32
__global__ __launch_bounds__(128) void gemm2_kernel(
    const float* __restrict__ W, int M) {
  __shared__ float As[G2_BK][64 + 4];
  __shared__ float Bs[G2_BK][48];

  const int t = threadIdx.x;
  const int row0 = blockIdx.x * 64;
  const int warp = t >> 5;
  const int lane = t & 31;
  const int g  = lane >> 2;
  const int tg = lane & 3;
  const int m_base = warp * 16;

  float acc[5][4];
#pragma unroll
  for (int nt = 0; nt < 5; nt++)
#pragma unroll
    for (int i = 0; i < 4; i++) acc[nt][i] = 0.f;

  for (int k0 = 0; k0 < HID; k0 += G2_BK) {
#pragma unroll
    for (int i = 0; i < 4; i++) {
      int id = t + i * 128;
      int r = id >> 3;
      int c8 = id & 7;
      int grow = row0 + r;
      float2 lo = make_float2(0.f, 0.f), hi = make_float2(0.f, 0.f);
      if (grow < M) {
        uint2 u = *(const uint2*)(g_agg1 + (size_t)grow * HID + k0 + c8 * 4);
        lo = __half22float2(*(__half2*)&u.x);
        hi = __half22float2(*(__half2*)&u.y);
      }
      As[c8 * 4 + 0][r] = lo.x;
      As[c8 * 4 + 1][r] = lo.y;
      As[c8 * 4 + 2][r] = hi.x;
      As[c8 * 4 + 3][r] = hi.y;
    }
#pragma unroll
    for (int i = 0; i < 10; i++) {
      int id = t + i * 128;
      int r = id / C_OUT, c = id % C_OUT;
      Bs[r][c] = __ldg(W + (size_t)(k0 + r) * C_OUT + c);
    }
    __syncthreads();

#pragma unroll
    for (int kk = 0; kk < G2_BK / 8; kk++) {
      uint32_t a[4];
      a[0] = f2tf32(As[kk * 8 + tg    ][m_base + g    ]);
      a[1] = f2tf32(As[kk * 8 + tg    ][m_base + g + 8]);
      a[2] = f2tf32(As[kk * 8 + tg + 4][m_base + g    ]);
      a[3] = f2tf32(As[kk * 8 + tg + 4][m_base + g + 8]);
#pragma unroll
      for (int nt = 0; nt < 5; nt++) {
        uint32_t b[2];
        b[0] = f2tf32(Bs[kk * 8 + tg    ][nt * 8 + g]);
        b[1] = f2tf32(Bs[kk * 8 + tg + 4][nt * 8 + g]);
        mma_tf32(acc[nt], a, b, acc[nt]);
      }
    }
    __syncthreads();
  }

  int r1 = row0 + m_base + g;
  int r2 = r1 + 8;
#pragma unroll
  for (int nt = 0; nt < 5; nt++) {
    int col = nt * 8 + tg * 2;
    if (r1 < M) *(__half2*)(g_h2 + (size_t)r1 * C_OUT + col) =
        __floats2half2_rn(acc[nt][0], acc[nt][1]);
    if (r2 < M) *(__half2*)(g_h2 + (size_t)r2 * C_OUT + col) =
        __floats2half2_rn(acc[nt][2], acc[nt][3]);
  }
}

// ---------------------------------------------------------------------------
// agg2 + bias + log_softmax, fused.
// ---------------------------------------------------------------------------
__global__ __launch_bounds__(256) void agg2_kernel(
    const float* __restrict__ b2, float* __restrict__ out, int M) {
  int row = blockIdx.x * 8 + (threadIdx.x >> 5);
  if (row >= M) return;
  int lane = threadIdx.x & 31;
  const bool has2 = lane < 8;
  int beg = g_rowptr[row];
  int end = g_rowptr[row + 1];

  float a0 = __ldg(b2 + lane);
  float a1 = has2 ? __ldg(b2 + lane + 32) : 0.f;

  int e = beg;
  for (; e + 4 <= end; e += 4) {
    uint2 c0 = __ldg(&g_csr[e]),     c1 = __ldg(&g_csr[e + 1]);
    uint2 c2 = __ldg(&g_csr[e + 2]), c3 = __ldg(&g_csr[e + 3]);
    float w0 = __uint_as_float(c0.y), w1 = __uint_as_float(c1.y);
    float w2 = __uint_as_float(c2.y), w3 = __uint_as_float(c3.y);
    const __half* p0 = g_h2 + (size_t)c0.x * C_OUT;
    const __half* p1 = g_h2 + (size_t)c1.x * C_OUT;
    const __half* p2 = g_h2 + (size_t)c2.x * C_OUT;
    const __half* p3 = g_h2 + (size_t)c3.x * C_OUT;
    float u0 = __half2float(p0[lane]);
    float u1 = __half2float(p1[lane]);
    float u2 = __half2float(p2[lane]);
    float u3 = __half2float(p3[lane]);
    a0 += w0 * u0 + w1 * u1 + w2 * u2 + w3 * u3;
    if (has2) {
      a1 += w0 * __half2float(p0[lane + 32]) + w1 * __half2float(p1[lane + 32])
          + w2 * __half2float(p2[lane + 32]) + w3 * __half2float(p3[lane + 32]);
    }
  }
  for (; e < end; e++) {
    uint2 c0 = __ldg(&g_csr[e]);
    float w0 = __uint_as_float(c0.y);
    const __half* p0 = g_h2 + (size_t)c0.x * C_OUT;
    a0 += w0 * __half2float(p0[lane]);
    if (has2) a1 += w0 * __half2float(p0[lane + 32]);
  }

  float m = has2 ? fmaxf(a0, a1) : a0;
#pragma unroll
  for (int o = 16; o; o >>= 1) m = fmaxf(m, __shfl_xor_sync(0xffffffffu, m, o));
  float s = expf(a0 - m) + (has2 ? expf(a1 - m) : 0.f);
#pragma unroll
  for (int o = 16; o; o >>= 1) s += __shfl_xor_sync(0xffffffffu, s, o);
  float lse = m + logf(s);

  float* p = out + (size_t)row * C_OUT;
  p[lane] = a0 - lse;
  if (has2) p[lane + 32] = a1 - lse;
}

// ---------------------------------------------------------------------------
// Single stream, linear chain (harness capture requires it).
// gemm1 placed 4th so ncu profiles it.
// ---------------------------------------------------------------------------
extern "C" void kernel_launch(void* const* d_in, const int* in_sizes, int n_in,
                              void* d_out, int out_size) {
  const float* x  = (const float*)d_in[0];
  const int*   ei = (const int*)d_in[1];   // int32
  const float* ew = (const float*)d_in[2];
  const float* W1 = (const float*)d_in[3];
  const float* b1 = (const float*)d_in[4];
  const float* W2 = (const float*)d_in[5];
  const float* b2 = (const float*)d_in[6];
  float* out      = (float*)d_out;

  const int M = in_sizes[0] / F_IN;
  const int E = in_sizes[2];
  const int nblk = (M + SCAN_BLK - 1) / SCAN_BLK;

  // CSR front half (independent of gemm1)
  zero_cnt_kernel<<<(M + 255) / 256, 256>>>(M);
  hist_kernel<<<(E / 4 + 255) / 256, 256>>>(ei + E, E);
  scanA_kernel<<<nblk, SCAN_BLK>>>(M);

  // gemm1 as 4th launch (profiling target)
  gemm1_kernel<<<(M + 127) / 128, 256>>>(x, W1, M);

  // CSR back half
  scanB_kernel<<<1, SCAN_BLK>>>(nblk, M, E);
  scanC_kernel<<<nblk, SCAN_BLK>>>(M);
  fill_kernel<<<(E / 2 + 255) / 256, 256>>>(ei, ew, E);

  // Layer 1 aggregation (fp16 gather) + bias + ReLU, fp16 out
  agg1_kernel<<<(M + 7) / 8, 256>>>(b1, M);

  // GEMM2 (tf32 MMA, fp16 in/out)
  gemm2_kernel<<<(M + 63) / 64, 128>>>(W2, M);

  // Layer 2 aggregation + bias + log_softmax
  agg2_kernel<<<(M + 7) / 8, 256>>>(b2, out, M);
}

// round 16
// speedup vs baseline: 1.0121x; 1.0121x over previous
#include <cuda_runtime.h>
#include <cuda_fp16.h>
#include <stdint.h>
#include <math.h>

#define F_IN  256
#define HID   128
#define C_OUT 40
#define NMAX  100000
#define EMAX  3200000
#define SCAN_BLK 1024

// Scratch (allocation-free rule: __device__ globals)
__device__ __half g_h1[(size_t)NMAX * HID];    // x @ W1, fp16
__device__ __half g_agg1[(size_t)NMAX * HID];  // relu(agg + b1), fp16
__device__ __half g_h2[(size_t)NMAX * C_OUT];  // agg1 @ W2, fp16

// CSR scratch
__device__ int   g_cnt[NMAX];
__device__ int   g_rowptr[NMAX + 1];
__device__ int   g_cursor[NMAX];
__device__ int   g_partial[(NMAX + SCAN_BLK - 1) / SCAN_BLK];
__device__ int   g_offs[(NMAX + SCAN_BLK - 1) / SCAN_BLK];
__device__ uint2 g_csr[EMAX];   // .x = src, .y = weight bits

// ---------------------------------------------------------------------------
// helpers
// ---------------------------------------------------------------------------
__device__ __forceinline__ uint32_t f2tf32(float x) {
  uint32_t r;
  asm("cvt.rna.tf32.f32 %0, %1;" : "=r"(r) : "f"(x));
  return r;
}

__device__ __forceinline__ void mma_tf32(
    float* d, const uint32_t* a, const uint32_t* b, const float* c) {
  asm volatile(
      "mma.sync.aligned.m16n8k8.row.col.f32.tf32.tf32.f32 "
      "{%0,%1,%2,%3}, {%4,%5,%6,%7}, {%8,%9}, {%10,%11,%12,%13};"
      : "=f"(d[0]), "=f"(d[1]), "=f"(d[2]), "=f"(d[3])
      : "r"(a[0]), "r"(a[1]), "r"(a[2]), "r"(a[3]),
        "r"(b[0]), "r"(b[1]),
        "f"(c[0]), "f"(c[1]), "f"(c[2]), "f"(c[3]));
}

__device__ __forceinline__ void mma_f16(
    float* d, const uint32_t* a, const uint32_t* b, const float* c) {
  asm volatile(
      "mma.sync.aligned.m16n8k16.row.col.f32.f16.f16.f32 "
      "{%0,%1,%2,%3}, {%4,%5,%6,%7}, {%8,%9}, {%10,%11,%12,%13};"
      : "=f"(d[0]), "=f"(d[1]), "=f"(d[2]), "=f"(d[3])
      : "r"(a[0]), "r"(a[1]), "r"(a[2]), "r"(a[3]),
        "r"(b[0]), "r"(b[1]),
        "f"(c[0]), "f"(c[1]), "f"(c[2]), "f"(c[3]));
}

__device__ __forceinline__ void ldsm_x4(uint32_t* r, uint32_t addr) {
  asm volatile("ldmatrix.sync.aligned.m8n8.x4.shared.b16 {%0,%1,%2,%3}, [%4];"
               : "=r"(r[0]), "=r"(r[1]), "=r"(r[2]), "=r"(r[3]) : "r"(addr));
}

__device__ __forceinline__ void ldsm_x4_trans(uint32_t* r, uint32_t addr) {
  asm volatile("ldmatrix.sync.aligned.m8n8.x4.trans.shared.b16 {%0,%1,%2,%3}, [%4];"
               : "=r"(r[0]), "=r"(r[1]), "=r"(r[2]), "=r"(r[3]) : "r"(addr));
}

// ---------------------------------------------------------------------------
// GEMM1: H1[M,128] = X[M,256] @ W1[256,128]
// fp16 MMA (m16n8k16) + ldmatrix, register double-buffered staging with
// fp16-converted prefetch regs. Block tile 64x128 (256 thr, 8 warps 2m x 4n,
// warp tile 32x32) -> ~100 regs -> 2 CTAs/SM for latency hiding.
// ---------------------------------------------------------------------------
#define G1_BK 32
__global__ __launch_bounds__(256) void gemm1_kernel(
    const float* __restrict__ X, const float* __restrict__ W, int M) {
  __shared__ __half As[64][G1_BK + 8];    // [m][k], 80B row
  __shared__ __half Bs[G1_BK][HID + 8];   // [k][n], 272B row

  const int t = threadIdx.x;
  const int row0 = blockIdx.x * 64;
  const int warp = t >> 5;
  const int lane = t & 31;
  const int g  = lane >> 2;
  const int tg = lane & 3;
  const int m_base = (warp & 1) * 32;
  const int n_base = (warp >> 1) * 32;
  const int l15 = lane & 15;
  const int lhi = (lane >> 4) << 3;  // 0 or 8

  // Staging coords: A = 1024 float2 (4/thread), B = 2048 float2 (8/thread)
  int arow[4], acol[4], brow[8], bcol[8];
  const float* aptr[4];
#pragma unroll
  for (int i = 0; i < 4; i++) {
    int id = t + i * 256;
    arow[i] = id >> 4;            // 0..63
    acol[i] = (id & 15) * 2;      // 0..30
    int grow = row0 + arow[i];
    if (grow >= M) grow = M - 1;
    aptr[i] = X + (size_t)grow * F_IN + acol[i];
  }
#pragma unroll
  for (int i = 0; i < 8; i++) {
    int id = t + i * 256;
    brow[i] = id >> 6;            // 0..31
    bcol[i] = (id & 63) * 2;      // 0..126
  }

  float acc[2][4][4];
#pragma unroll
  for (int mt = 0; mt < 2; mt++)
#pragma unroll
    for (int nt = 0; nt < 4; nt++)
#pragma unroll
      for (int i = 0; i < 4; i++) acc[mt][nt][i] = 0.f;

  // Prologue: load + convert chunk 0 (fp16-packed regs: 12 total)
  uint32_t aReg[4], bReg[8];
#pragma unroll
  for (int i = 0; i < 4; i++) {
    float2 v = *(const float2*)(aptr[i]);
    __half2 h = __floats2half2_rn(v.x, v.y);
    aReg[i] = *(uint32_t*)&h;
  }
#pragma unroll
  for (int i = 0; i < 8; i++) {
    float2 v = *(const float2*)(W + (size_t)brow[i] * HID + bcol[i]);
    __half2 h = __floats2half2_rn(v.x, v.y);
    bReg[i] = *(uint32_t*)&h;
  }

  const int NCHUNK = F_IN / G1_BK;  // 8
#pragma unroll 1
  for (int c = 0; c < NCHUNK; c++) {
    // Store current chunk regs -> smem
#pragma unroll
    for (int i = 0; i < 4; i++)
      *(uint32_t*)&As[arow[i]][acol[i]] = aReg[i];
#pragma unroll
    for (int i = 0; i < 8; i++)
      *(uint32_t*)&Bs[brow[i]][bcol[i]] = bReg[i];
    __syncthreads();

    // Prefetch next chunk (overlaps MMAs below)
    if (c + 1 < NCHUNK) {
      int k0n = (c + 1) * G1_BK;
#pragma unroll
      for (int i = 0; i < 4; i++) {
        float2 v = *(const float2*)(aptr[i] + k0n);
        __half2 h = __floats2half2_rn(v.x, v.y);
        aReg[i] = *(uint32_t*)&h;
      }
#pragma unroll
      for (int i = 0; i < 8; i++) {
        float2 v = *(const float2*)(W + (size_t)(k0n + brow[i]) * HID + bcol[i]);
        __half2 h = __floats2half2_rn(v.x, v.y);
        bReg[i] = *(uint32_t*)&h;
      }
    }

    // Compute chunk c: 2 k16 steps x (2 LDSM A + 2 LDSM.T B + 8 MMA)
#pragma unroll
    for (int kk = 0; kk < 2; kk++) {
      const int kb = kk * 16;
      uint32_t a[2][4];
#pragma unroll
      for (int mt = 0; mt < 2; mt++) {
        uint32_t addr = (uint32_t)__cvta_generic_to_shared(
            &As[m_base + mt * 16 + l15][kb + lhi]);
        ldsm_x4(a[mt], addr);
      }
#pragma unroll
      for (int p = 0; p < 2; p++) {   // 2 n16 pairs -> 4 n8 tiles
        uint32_t b[4];
        uint32_t addr = (uint32_t)__cvta_generic_to_shared(
            &Bs[kb + l15][n_base + p * 16 + lhi]);
        ldsm_x4_trans(b, addr);
        mma_f16(acc[0][2 * p    ], a[0], b + 0, acc[0][2 * p    ]);
        mma_f16(acc[0][2 * p + 1], a[0], b + 2, acc[0][2 * p + 1]);
        mma_f16(acc[1][2 * p    ], a[1], b + 0, acc[1][2 * p    ]);
        mma_f16(acc[1][2 * p + 1], a[1], b + 2, acc[1][2 * p + 1]);
      }
    }
    __syncthreads();
  }

#pragma unroll
  for (int mt = 0; mt < 2; mt++) {
    int r1 = row0 + m_base + mt * 16 + g;
    int r2 = r1 + 8;
#pragma unroll
    for (int nt = 0; nt < 4; nt++) {
      int col = n_base + nt * 8 + tg * 2;
      if (r1 < M) *(__half2*)(g_h1 + (size_t)r1 * HID + col) =
          __floats2half2_rn(acc[mt][nt][0], acc[mt][nt][1]);
      if (r2 < M) *(__half2*)(g_h1 + (size_t)r2 * HID + col) =
          __floats2half2_rn(acc[mt][nt][2], acc[mt][nt][3]);
    }
  }
}

// ---------------------------------------------------------------------------
// CSR build (R7-proven 3-phase scan; single stream)
// ---------------------------------------------------------------------------
__global__ void zero_cnt_kernel(int M) {
  int i = blockIdx.x * blockDim.x + threadIdx.x;
  if (i < M) g_cnt[i] = 0;
}

__global__ void hist_kernel(const int* __restrict__ dst4, int E) {
  int i = blockIdx.x * blockDim.x + threadIdx.x;
  int e = i * 4;
  if (e + 4 <= E) {
    int4 d = *(const int4*)(dst4 + e);
    atomicAdd(&g_cnt[d.x], 1);
    atomicAdd(&g_cnt[d.y], 1);
    atomicAdd(&g_cnt[d.z], 1);
    atomicAdd(&g_cnt[d.w], 1);
  } else {
    for (; e < E; e++) atomicAdd(&g_cnt[__ldg(dst4 + e)], 1);
  }
}

__global__ __launch_bounds__(SCAN_BLK) void scanA_kernel(int M) {
  __shared__ int s[SCAN_BLK];
  int t = threadIdx.x;
  int i = blockIdx.x * SCAN_BLK + t;
  int v = (i < M) ? g_cnt[i] : 0;
  s[t] = v;
  __syncthreads();
#pragma unroll
  for (int d = SCAN_BLK / 2; d > 0; d >>= 1) {
    if (t < d) s[t] += s[t + d];
    __syncthreads();
  }
  if (t == 0) g_partial[blockIdx.x] = s[0];
}

__global__ __launch_bounds__(SCAN_BLK) void scanB_kernel(int nblk, int M, int E) {
  __shared__ int s[2][SCAN_BLK];
  int t = threadIdx.x;
  int v = (t < nblk) ? g_partial[t] : 0;
  s[0][t] = v;
  __syncthreads();
  int cur = 0;
#pragma unroll
  for (int d = 1; d < SCAN_BLK; d <<= 1) {
    int nxt = cur ^ 1;
    int val = s[cur][t];
    if (t >= d) val += s[cur][t - d];
    s[nxt][t] = val;
    __syncthreads();
    cur = nxt;
  }
  if (t < nblk) g_offs[t] = s[cur][t] - v;
  if (t == 0) g_rowptr[M] = E;
}

__global__ __launch_bounds__(SCAN_BLK) void scanC_kernel(int M) {
  __shared__ int s[2][SCAN_BLK];
  int t = threadIdx.x;
  int i = blockIdx.x * SCAN_BLK + t;
  int v = (i < M) ? g_cnt[i] : 0;
  s[0][t] = v;
  __syncthreads();
  int cur = 0;
#pragma unroll
  for (int d = 1; d < SCAN_BLK; d <<= 1) {
    int nxt = cur ^ 1;
    int val = s[cur][t];
    if (t >= d) val += s[cur][t - d];
    s[nxt][t] = val;
    __syncthreads();
    cur = nxt;
  }
  if (i < M) {
    int excl = s[cur][t] - v + g_offs[blockIdx.x];
    g_rowptr[i] = excl;
    g_cursor[i] = excl;
  }
}

__global__ void fill_kernel(const int* __restrict__ ei,
                            const float* __restrict__ ew, int E) {
  int i = blockIdx.x * blockDim.x + threadIdx.x;
  int e = i * 2;
  if (e + 2 <= E) {
    int2   s = *(const int2*)(ei + e);
    int2   d = *(const int2*)(ei + E + e);
    float2 w = *(const float2*)(ew + e);
    int p0 = atomicAdd(&g_cursor[d.x], 1);
    g_csr[p0] = make_uint2((unsigned)s.x, __float_as_uint(w.x));
    int p1 = atomicAdd(&g_cursor[d.y], 1);
    g_csr[p1] = make_uint2((unsigned)s.y, __float_as_uint(w.y));
  } else {
    for (; e < E; e++) {
      int src = __ldg(ei + e);
      int dst = __ldg(ei + E + e);
      int pos = atomicAdd(&g_cursor[dst], 1);
      g_csr[pos] = make_uint2((unsigned)src, __float_as_uint(__ldg(ew + e)));
    }
  }
}

// ---------------------------------------------------------------------------
// agg1: one warp per dst row; fp16 gather, fp32 accumulate; unroll 8 (MLP).
// Fused: +b1, ReLU; output stored fp16.
// ---------------------------------------------------------------------------
__device__ __forceinline__ void acc_h1(float4& acc, float w, uint2 u) {
  float2 lo = __half22float2(*(__half2*)&u.x);
  float2 hi = __half22float2(*(__half2*)&u.y);
  acc.x += w * lo.x; acc.y += w * lo.y;
  acc.z += w * hi.x; acc.w += w * hi.y;
}

__global__ __launch_bounds__(256) void agg1_kernel(
    const float* __restrict__ b1, int M) {
  int row = blockIdx.x * 8 + (threadIdx.x >> 5);
  if (row >= M) return;
  int lane = threadIdx.x & 31;
  int beg = g_rowptr[row];
  int end = g_rowptr[row + 1];

  float4 acc = *(const float4*)(b1 + lane * 4);

  const uint2* h1p = (const uint2*)g_h1;
  int e = beg;
  for (; e + 8 <= end; e += 8) {
    uint2 c0 = __ldg(&g_csr[e]),     c1 = __ldg(&g_csr[e + 1]);
    uint2 c2 = __ldg(&g_csr[e + 2]), c3 = __ldg(&g_csr[e + 3]);
    uint2 c4 = __ldg(&g_csr[e + 4]), c5 = __ldg(&g_csr[e + 5]);
    uint2 c6 = __ldg(&g_csr[e + 6]), c7 = __ldg(&g_csr[e + 7]);
    uint2 u0 = __ldg(h1p + (size_t)c0.x * 32 + lane);
    uint2 u1 = __ldg(h1p + (size_t)c1.x * 32 + lane);
    uint2 u2 = __ldg(h1p + (size_t)c2.x * 32 + lane);
    uint2 u3 = __ldg(h1p + (size_t)c3.x * 32 + lane);
    uint2 u4 = __ldg(h1p + (size_t)c4.x * 32 + lane);
    uint2 u5 = __ldg(h1p + (size_t)c5.x * 32 + lane);
    uint2 u6 = __ldg(h1p + (size_t)c6.x * 32 + lane);
    uint2 u7 = __ldg(h1p + (size_t)c7.x * 32 + lane);
    acc_h1(acc, __uint_as_float(c0.y), u0);
    acc_h1(acc, __uint_as_float(c1.y), u1);
    acc_h1(acc, __uint_as_float(c2.y), u2);
    acc_h1(acc, __uint_as_float(c3.y), u3);
    acc_h1(acc, __uint_as_float(c4.y), u4);
    acc_h1(acc, __uint_as_float(c5.y), u5);
    acc_h1(acc, __uint_as_float(c6.y), u6);
    acc_h1(acc, __uint_as_float(c7.y), u7);
  }
  for (; e < end; e++) {
    uint2 c0 = __ldg(&g_csr[e]);
    uint2 u0 = __ldg(h1p + (size_t)c0.x * 32 + lane);
    acc_h1(acc, __uint_as_float(c0.y), u0);
  }
  acc.x = fmaxf(acc.x, 0.f); acc.y = fmaxf(acc.y, 0.f);
  acc.z = fmaxf(acc.z, 0.f); acc.w = fmaxf(acc.w, 0.f);
  __half2 h01 = __floats2half2_rn(acc.x, acc.y);
  __half2 h23 = __floats2half2_rn(acc.z, acc.w);
  uint2 pack = make_uint2(*(uint32_t*)&h01, *(uint32_t*)&h23);
  *(uint2*)(g_agg1 + (size_t)row * HID + lane * 4) = pack;
}

// ---------------------------------------------------------------------------
// GEMM2: H2[M,40] = agg1[M,128] @ W2[128,40], tf32 MMA (RNA cvt), fp16 in/out.
// ---------------------------------------------------------------------------
#define G2_BK 32
__global__ __launch_bounds__(128) void gemm2_kernel(
    const float* __restrict__ W, int M) {
  __shared__ float As[G2_BK][64 + 4];
  __shared__ float Bs[G2_BK][48];

  const int t = threadIdx.x;
  const int row0 = blockIdx.x * 64;
  const int warp = t >> 5;
  const int lane = t & 31;
  const int g  = lane >> 2;
  const int tg = lane & 3;
  const int m_base = warp * 16;

  float acc[5][4];
#pragma unroll
  for (int nt = 0; nt < 5; nt++)
#pragma unroll
    for (int i = 0; i < 4; i++) acc[nt][i] = 0.f;

  for (int k0 = 0; k0 < HID; k0 += G2_BK) {
#pragma unroll
    for (int i = 0; i < 4; i++) {
      int id = t + i * 128;
      int r = id >> 3;
      int c8 = id & 7;
      int grow = row0 + r;
      float2 lo = make_float2(0.f, 0.f), hi = make_float2(0.f, 0.f);
      if (grow < M) {
        uint2 u = *(const uint2*)(g_agg1 + (size_t)grow * HID + k0 + c8 * 4);
        lo = __half22float2(*(__half2*)&u.x);
        hi = __half22float2(*(__half2*)&u.y);
      }
      As[c8 * 4 + 0][r] = lo.x;
      As[c8 * 4 + 1][r] = lo.y;
      As[c8 * 4 + 2][r] = hi.x;
      As[c8 * 4 + 3][r] = hi.y;
    }
#pragma unroll
    for (int i = 0; i < 10; i++) {
      int id = t + i * 128;
      int r = id / C_OUT, c = id % C_OUT;
      Bs[r][c] = __ldg(W + (size_t)(k0 + r) * C_OUT + c);
    }
    __syncthreads();

#pragma unroll
    for (int kk = 0; kk < G2_BK / 8; kk++) {
      uint32_t a[4];
      a[0] = f2tf32(As[kk * 8 + tg    ][m_base + g    ]);
      a[1] = f2tf32(As[kk * 8 + tg    ][m_base + g + 8]);
      a[2] = f2tf32(As[kk * 8 + tg + 4][m_base + g    ]);
      a[3] = f2tf32(As[kk * 8 + tg + 4][m_base + g + 8]);
#pragma unroll
      for (int nt = 0; nt < 5; nt++) {
        uint32_t b[2];
        b[0] = f2tf32(Bs[kk * 8 + tg    ][nt * 8 + g]);
        b[1] = f2tf32(Bs[kk * 8 + tg + 4][nt * 8 + g]);
        mma_tf32(acc[nt], a, b, acc[nt]);
      }
    }
    __syncthreads();
  }

  int r1 = row0 + m_base + g;
  int r2 = r1 + 8;
#pragma unroll
  for (int nt = 0; nt < 5; nt++) {
    int col = nt * 8 + tg * 2;
    if (r1 < M) *(__half2*)(g_h2 + (size_t)r1 * C_OUT + col) =
        __floats2half2_rn(acc[nt][0], acc[nt][1]);
    if (r2 < M) *(__half2*)(g_h2 + (size_t)r2 * C_OUT + col) =
        __floats2half2_rn(acc[nt][2], acc[nt][3]);
  }
}

// ---------------------------------------------------------------------------
// agg2 + bias + log_softmax, fused.
// ---------------------------------------------------------------------------
__global__ __launch_bounds__(256) void agg2_kernel(
    const float* __restrict__ b2, float* __restrict__ out, int M) {
  int row = blockIdx.x * 8 + (threadIdx.x >> 5);
  if (row >= M) return;
  int lane = threadIdx.x & 31;
  const bool has2 = lane < 8;
  int beg = g_rowptr[row];
  int end = g_rowptr[row + 1];

  float a0 = __ldg(b2 + lane);
  float a1 = has2 ? __ldg(b2 + lane + 32) : 0.f;

  int e = beg;
  for (; e + 4 <= end; e += 4) {
    uint2 c0 = __ldg(&g_csr[e]),     c1 = __ldg(&g_csr[e + 1]);
    uint2 c2 = __ldg(&g_csr[e + 2]), c3 = __ldg(&g_csr[e + 3]);
    float w0 = __uint_as_float(c0.y), w1 = __uint_as_float(c1.y);
    float w2 = __uint_as_float(c2.y), w3 = __uint_as_float(c3.y);
    const __half* p0 = g_h2 + (size_t)c0.x * C_OUT;
    const __half* p1 = g_h2 + (size_t)c1.x * C_OUT;
    const __half* p2 = g_h2 + (size_t)c2.x * C_OUT;
    const __half* p3 = g_h2 + (size_t)c3.x * C_OUT;
    float u0 = __half2float(p0[lane]);
    float u1 = __half2float(p1[lane]);
    float u2 = __half2float(p2[lane]);
    float u3 = __half2float(p3[lane]);
    a0 += w0 * u0 + w1 * u1 + w2 * u2 + w3 * u3;
    if (has2) {
      a1 += w0 * __half2float(p0[lane + 32]) + w1 * __half2float(p1[lane + 32])
          + w2 * __half2float(p2[lane + 32]) + w3 * __half2float(p3[lane + 32]);
    }
  }
  for (; e < end; e++) {
    uint2 c0 = __ldg(&g_csr[e]);
    float w0 = __uint_as_float(c0.y);
    const __half* p0 = g_h2 + (size_t)c0.x * C_OUT;
    a0 += w0 * __half2float(p0[lane]);
    if (has2) a1 += w0 * __half2float(p0[lane + 32]);
  }

  float m = has2 ? fmaxf(a0, a1) : a0;
#pragma unroll
  for (int o = 16; o; o >>= 1) m = fmaxf(m, __shfl_xor_sync(0xffffffffu, m, o));
  float s = expf(a0 - m) + (has2 ? expf(a1 - m) : 0.f);
#pragma unroll
  for (int o = 16; o; o >>= 1) s += __shfl_xor_sync(0xffffffffu, s, o);
  float lse = m + logf(s);

  float* p = out + (size_t)row * C_OUT;
  p[lane] = a0 - lse;
  if (has2) p[lane + 32] = a1 - lse;
}

// ---------------------------------------------------------------------------
// Single stream, linear chain (harness capture requires it).
// gemm1 placed 4th so ncu profiles it.
// ---------------------------------------------------------------------------
extern "C" void kernel_launch(void* const* d_in, const int* in_sizes, int n_in,
                              void* d_out, int out_size) {
  const float* x  = (const float*)d_in[0];
  const int*   ei = (const int*)d_in[1];   // int32
  const float* ew = (const float*)d_in[2];
  const float* W1 = (const float*)d_in[3];
  const float* b1 = (const float*)d_in[4];
  const float* W2 = (const float*)d_in[5];
  const float* b2 = (const float*)d_in[6];
  float* out      = (float*)d_out;

  const int M = in_sizes[0] / F_IN;
  const int E = in_sizes[2];
  const int nblk = (M + SCAN_BLK - 1) / SCAN_BLK;

  // CSR front half (independent of gemm1)
  zero_cnt_kernel<<<(M + 255) / 256, 256>>>(M);
  hist_kernel<<<(E / 4 + 255) / 256, 256>>>(ei + E, E);
  scanA_kernel<<<nblk, SCAN_BLK>>>(M);

  // gemm1 as 4th launch (profiling target)
  gemm1_kernel<<<(M + 63) / 64, 256>>>(x, W1, M);

  // CSR back half
  scanB_kernel<<<1, SCAN_BLK>>>(nblk, M, E);
  scanC_kernel<<<nblk, SCAN_BLK>>>(M);
  fill_kernel<<<(E / 2 + 255) / 256, 256>>>(ei, ew, E);

  // Layer 1 aggregation (fp16 gather) + bias + ReLU, fp16 out
  agg1_kernel<<<(M + 7) / 8, 256>>>(b1, M);

  // GEMM2 (tf32 MMA, fp16 in/out)
  gemm2_kernel<<<(M + 63) / 64, 128>>>(W2, M);

  // Layer 2 aggregation + bias + log_softmax
  agg2_kernel<<<(M + 7) / 8, 256>>>(b2, out, M);
}